// round 8
// baseline (speedup 1.0000x reference)
#include <cuda_runtime.h>
#include <cuda_fp16.h>
#include <math.h>

constexpr int NA = 50000;
constexpr int NT = 25000;
constexpr int DIN = 32;
constexpr int H = 64;
constexpr int E_AA = 800000;
constexpr int E_AT = 400000;
constexpr int E_TA = 400000;

constexpr int OFF_AA   = 0;
constexpr int OFF_AT_S = NA;
constexpr int OFF_TA_D = 2 * NA;
constexpr int OFF_AT_D = 3 * NA;
constexpr int OFF_TA_S = 3 * NA + NT;
constexpr int NTOT = 3 * NA + 2 * NT;

constexpr int NBLK_A = (NA + 1023) / 1024;
constexpr int NBLK_T = (NT + 1023) / 1024;
constexpr int NBLK   = NBLK_A + NBLK_T;

// scratch
__device__ int    g_cnt[NTOT];
__device__ float  g_dis[NTOT];
__device__ __half g_x16[(size_t)(NA + NT) * DIN];   // raw features fp16 (unified rows)
__device__ __half g_f16[(size_t)(NA + NT) * H];     // relu(layer1) fp16 (unified rows)
__device__ float  g_agg1a[(size_t)NA * 64];         // [A_aa(32) | A_ta(32)] per agent
__device__ float  g_agg1t[(size_t)NT * 32];         // A_at per target
__device__ float  g_agg2a[(size_t)NA * 128];        // [B_aa(64) | B_ta(64)] per agent
__device__ float  g_agg2t[(size_t)NT * 64];         // B_at per target
// CSR (built once per launch; shared by both layers)
__device__ int  g_rs_a[NA + 1];
__device__ int  g_rs_t[NT + 1];
__device__ int  g_cur_a[NA];
__device__ int  g_cur_t[NT];
__device__ int2 g_ent_a[E_AA + E_TA];               // {unified src idx, w bits}
__device__ int2 g_ent_t[E_AT];                      // {agent src idx, w bits}
__device__ int  g_part[NBLK];
__device__ int  g_partscan[NBLK];

// ---------------------------------------------------------------------------
__global__ void zero_cnt_kernel() {
    int i = blockIdx.x * blockDim.x + threadIdx.x;
    if (i < NTOT) g_cnt[i] = 0;
}

__global__ void count_all_kernel(const int* __restrict__ dst_aa,
                                 const int* __restrict__ src_at,
                                 const int* __restrict__ dst_at,
                                 const int* __restrict__ src_ta,
                                 const int* __restrict__ dst_ta) {
    constexpr int G_AA = E_AA / 4, G_AT = E_AT / 4, G_TA = E_TA / 4;
    int i = blockIdx.x * blockDim.x + threadIdx.x;
    const int* p; int off, j;
    if (i < G_AA)                           { p = dst_aa; off = OFF_AA;   j = i; }
    else if (i < G_AA + G_AT)               { p = src_at; off = OFF_AT_S; j = i - G_AA; }
    else if (i < G_AA + 2 * G_AT)           { p = dst_at; off = OFF_AT_D; j = i - G_AA - G_AT; }
    else if (i < G_AA + 2 * G_AT + G_TA)    { p = src_ta; off = OFF_TA_S; j = i - G_AA - 2 * G_AT; }
    else if (i < G_AA + 2 * G_AT + 2*G_TA)  { p = dst_ta; off = OFF_TA_D; j = i - G_AA - 2 * G_AT - G_TA; }
    else return;
    int4 v = *(const int4*)(p + j * 4);
    atomicAdd(&g_cnt[off + v.x], 1);
    atomicAdd(&g_cnt[off + v.y], 1);
    atomicAdd(&g_cnt[off + v.z], 1);
    atomicAdd(&g_cnt[off + v.w], 1);
}

__global__ void dis_kernel() {
    int i = blockIdx.x * blockDim.x + threadIdx.x;
    if (i >= NTOT) return;
    int c = g_cnt[i];
    float d;
    if (i < NA) d = rsqrtf((float)c + 1.0f);
    else        d = (c > 0) ? rsqrtf((float)c) : 0.0f;
    g_dis[i] = d;
}

// cast inputs to fp16 unified buffer
__global__ void cast_kernel(const float4* __restrict__ xa, const float4* __restrict__ xt) {
    constexpr int TOT = (NA + NT) * (DIN / 4);
    int i = blockIdx.x * blockDim.x + threadIdx.x;
    if (i >= TOT) return;
    int row = i >> 3, j = i & 7;
    float4 v = (row < NA) ? xa[(size_t)row * 8 + j] : xt[(size_t)(row - NA) * 8 + j];
    __half2 h0 = __floats2half2_rn(v.x, v.y);
    __half2 h1 = __floats2half2_rn(v.z, v.w);
    uint2 u; u.x = *(unsigned*)&h0; u.y = *(unsigned*)&h1;
    *(uint2*)(g_x16 + (size_t)row * DIN + j * 4) = u;
}

// scan phase 1
__global__ __launch_bounds__(1024) void scan_local_kernel() {
    __shared__ int sm[1024];
    int b = blockIdx.x;
    bool isA = (b < NBLK_A);
    int base = isA ? b * 1024 : (b - NBLK_A) * 1024;
    int n = isA ? NA : NT;
    int tid = threadIdx.x;
    int i = base + tid;
    int v = 0;
    if (i < n) {
        if (isA) { v = g_cnt[OFF_AA + i] + g_cnt[OFF_TA_D + i]; g_cur_a[i] = 0; }
        else     { v = g_cnt[OFF_AT_D + i];                     g_cur_t[i] = 0; }
    }
    sm[tid] = v;
    __syncthreads();
#pragma unroll
    for (int off = 1; off < 1024; off <<= 1) {
        int u = (tid >= off) ? sm[tid - off] : 0;
        __syncthreads();
        sm[tid] += u;
        __syncthreads();
    }
    if (i < n) {
        int excl = sm[tid] - v;
        if (isA) g_rs_a[i] = excl; else g_rs_t[i] = excl;
    }
    if (tid == 1023) g_part[b] = sm[1023];
}

// scan phase 2
__global__ void scan_mid_kernel() {
    __shared__ int sp[NBLK];
    __shared__ int so[NBLK + 2];
    int tid = threadIdx.x;
    if (tid < NBLK) sp[tid] = g_part[tid];
    __syncthreads();
    if (tid == 0) {
        int s = 0;
        for (int b = 0; b < NBLK_A; b++) { so[b] = s; s += sp[b]; }
        so[NBLK] = s;
        s = 0;
        for (int b = NBLK_A; b < NBLK; b++) { so[b] = s; s += sp[b]; }
        so[NBLK + 1] = s;
    }
    __syncthreads();
    if (tid < NBLK) g_partscan[tid] = so[tid];
    if (tid == 0) { g_rs_a[NA] = so[NBLK]; g_rs_t[NT] = so[NBLK + 1]; }
}

// scan phase 3
__global__ __launch_bounds__(1024) void scan_add_kernel() {
    int b = blockIdx.x;
    if (b == 0) return;
    bool isA = (b < NBLK_A);
    if (!isA && b == NBLK_A) return;
    int base = isA ? b * 1024 : (b - NBLK_A) * 1024;
    int n = isA ? NA : NT;
    int i = base + threadIdx.x;
    int off = g_partscan[b];
    if (i < n) { if (isA) g_rs_a[i] += off; else g_rs_t[i] += off; }
}

__global__ void fill_kernel(const int* __restrict__ src_aa, const int* __restrict__ dst_aa,
                            const int* __restrict__ src_ta, const int* __restrict__ dst_ta,
                            const int* __restrict__ src_at, const int* __restrict__ dst_at) {
    int i = blockIdx.x * blockDim.x + threadIdx.x;
    if (i < E_AA) {
        int s = src_aa[i], d = dst_aa[i];
        float w = g_dis[OFF_AA + s] * g_dis[OFF_AA + d];
        int pos = g_rs_a[d] + atomicAdd(&g_cur_a[d], 1);
        g_ent_a[pos] = make_int2(s, __float_as_int(w));
    } else if (i < E_AA + E_TA) {
        int j = i - E_AA;
        int s = src_ta[j], d = dst_ta[j];
        float w = g_dis[OFF_TA_S + s] * g_dis[OFF_TA_D + d];
        int pos = g_rs_a[d] + atomicAdd(&g_cur_a[d], 1);
        g_ent_a[pos] = make_int2(NA + s, __float_as_int(w));
    } else if (i < E_AA + E_TA + E_AT) {
        int j = i - E_AA - E_TA;
        int s = src_at[j], d = dst_at[j];
        float w = g_dis[OFF_AT_S + s] * g_dis[OFF_AT_D + d];
        int pos = g_rs_t[d] + atomicAdd(&g_cur_t[d], 1);
        g_ent_t[pos] = make_int2(s, __float_as_int(w));
    }
}

// Aggregate raw fp16 features per relation. Warp per dst node, 4 edges in flight,
// 8 lanes/edge. Agents keep two accumulators (first vs second relation by src idx).
template <int FEAT>
__global__ __launch_bounds__(256) void agg_kernel(const __half* __restrict__ feat,
                                                  float* __restrict__ agg_a,
                                                  float* __restrict__ agg_t) {
    constexpr int NR = FEAT / 8;
    int gw = (blockIdx.x * 256 + threadIdx.x) >> 5;
    int lane = threadIdx.x & 31;
    int grp = lane >> 3, sub = lane & 7;
    float a1[NR], a2[NR];
#pragma unroll
    for (int r = 0; r < NR; r++) { a1[r] = 0.f; a2[r] = 0.f; }
    if (gw < NA) {
        int beg = g_rs_a[gw], end = g_rs_a[gw + 1];
        for (int p = beg + grp; p < end; p += 4) {
            int2 ent = __ldg(&g_ent_a[p]);
            float w = __int_as_float(ent.y);
            float m1 = (ent.x < NA) ? w : 0.f;
            float m2 = w - m1;
            float v[NR];
            if (FEAT == 32) {
                uint2 raw = *(const uint2*)(feat + (size_t)ent.x * FEAT + sub * 4);
                float2 f0 = __half22float2(*(__half2*)&raw.x);
                float2 f1 = __half22float2(*(__half2*)&raw.y);
                v[0] = f0.x; v[1] = f0.y; v[2] = f1.x; v[3] = f1.y;
            } else {
                uint4 raw = *(const uint4*)(feat + (size_t)ent.x * FEAT + sub * 8);
                float2 f0 = __half22float2(*(__half2*)&raw.x);
                float2 f1 = __half22float2(*(__half2*)&raw.y);
                float2 f2 = __half22float2(*(__half2*)&raw.z);
                float2 f3 = __half22float2(*(__half2*)&raw.w);
                v[0] = f0.x; v[1] = f0.y; v[2] = f1.x; v[3] = f1.y;
                v[4] = f2.x; v[5] = f2.y; v[6] = f3.x; v[7] = f3.y;
            }
#pragma unroll
            for (int r = 0; r < NR; r++) {
                a1[r] = fmaf(v[r], m1, a1[r]);
                a2[r] = fmaf(v[r], m2, a2[r]);
            }
        }
#pragma unroll
        for (int r = 0; r < NR; r++) {
            a1[r] += __shfl_down_sync(0xFFFFFFFFu, a1[r], 16);
            a1[r] += __shfl_down_sync(0xFFFFFFFFu, a1[r], 8);
            a2[r] += __shfl_down_sync(0xFFFFFFFFu, a2[r], 16);
            a2[r] += __shfl_down_sync(0xFFFFFFFFu, a2[r], 8);
        }
        if (grp == 0) {
            float* o1 = agg_a + (size_t)gw * (2 * FEAT) + sub * NR;
            float* o2 = o1 + FEAT;
#pragma unroll
            for (int q = 0; q < NR; q += 4) {
                *(float4*)(o1 + q) = make_float4(a1[q], a1[q+1], a1[q+2], a1[q+3]);
                *(float4*)(o2 + q) = make_float4(a2[q], a2[q+1], a2[q+2], a2[q+3]);
            }
        }
    } else if (gw < NA + NT) {
        int node = gw - NA;
        int beg = g_rs_t[node], end = g_rs_t[node + 1];
        for (int p = beg + grp; p < end; p += 4) {
            int2 ent = __ldg(&g_ent_t[p]);
            float w = __int_as_float(ent.y);
            float v[NR];
            if (FEAT == 32) {
                uint2 raw = *(const uint2*)(feat + (size_t)ent.x * FEAT + sub * 4);
                float2 f0 = __half22float2(*(__half2*)&raw.x);
                float2 f1 = __half22float2(*(__half2*)&raw.y);
                v[0] = f0.x; v[1] = f0.y; v[2] = f1.x; v[3] = f1.y;
            } else {
                uint4 raw = *(const uint4*)(feat + (size_t)ent.x * FEAT + sub * 8);
                float2 f0 = __half22float2(*(__half2*)&raw.x);
                float2 f1 = __half22float2(*(__half2*)&raw.y);
                float2 f2 = __half22float2(*(__half2*)&raw.z);
                float2 f3 = __half22float2(*(__half2*)&raw.w);
                v[0] = f0.x; v[1] = f0.y; v[2] = f1.x; v[3] = f1.y;
                v[4] = f2.x; v[5] = f2.y; v[6] = f3.x; v[7] = f3.y;
            }
#pragma unroll
            for (int r = 0; r < NR; r++) a1[r] = fmaf(v[r], w, a1[r]);
        }
#pragma unroll
        for (int r = 0; r < NR; r++) {
            a1[r] += __shfl_down_sync(0xFFFFFFFFu, a1[r], 16);
            a1[r] += __shfl_down_sync(0xFFFFFFFFu, a1[r], 8);
        }
        if (grp == 0) {
            float* o = agg_t + (size_t)node * FEAT + sub * NR;
#pragma unroll
            for (int q = 0; q < NR; q += 4)
                *(float4*)(o + q) = make_float4(a1[q], a1[q+1], a1[q+2], a1[q+3]);
        }
    }
}

// Node GEMM: y[64 rows, 64 cols] = xs @ Ws + bias.
// SELF: input = [Afirst + d^2 * selff | Asecond], stacked weights [Wa; Wb].
// PROJ: epilogue projects to 2 outputs with Wp/bp and writes out; else relu->fp16 fout.
// xs stored transposed with pad to kill LDS bank conflicts.
template <int K, bool SELF, bool PROJ>
__global__ __launch_bounds__(256) void gemm_kernel(
        const float* __restrict__ agg, const __half* __restrict__ selff,
        int n, int row_off,
        const float* __restrict__ Wa, const float* __restrict__ Wb,
        const float* __restrict__ ba, const float* __restrict__ bb,
        const float* __restrict__ Wp, const float* __restrict__ bp,
        __half* __restrict__ fout, float* __restrict__ out) {
    constexpr int KT  = (K < 64) ? K : 64;
    constexpr int NCH = K / KT;
    constexpr int SD  = SELF ? (K / 2) : 1;   // self feature dim (dummy 1 if unused)
    __shared__ float xs[KT][65];
    __shared__ float Ws[KT][64];
    __shared__ float bias[64];
    int tid = threadIdx.x;
    int row0 = blockIdx.x * 64;
    if (tid < 64) bias[tid] = ba[tid] + (SELF ? bb[tid] : 0.f);
    int ty = tid >> 4, tx = tid & 15;
    int r0 = ty * 4, c0 = tx * 4;
    float acc[4][4];
#pragma unroll
    for (int i = 0; i < 4; i++)
#pragma unroll
        for (int j = 0; j < 4; j++) acc[i][j] = 0.f;

    for (int ch = 0; ch < NCH; ch++) {
        for (int i = tid; i < KT * 64; i += 256) {
            int k = i >> 6, c = i & 63;
            int kk = ch * KT + k;
            float w;
            if (SELF) w = (kk < K / 2) ? Wa[kk * 64 + c] : Wb[(kk - K / 2) * 64 + c];
            else      w = Wa[kk * 64 + c];
            Ws[k][c] = w;
        }
        constexpr int KV = KT / 4;
        for (int i = tid; i < 64 * KV; i += 256) {
            int r = i / KV, kv = i - r * KV;
            int row = row0 + r;
            float4 v = (row < n) ? *(const float4*)(agg + (size_t)row * K + ch * KT + kv * 4)
                                 : make_float4(0.f, 0.f, 0.f, 0.f);
            xs[kv * 4 + 0][r] = v.x;
            xs[kv * 4 + 1][r] = v.y;
            xs[kv * 4 + 2][r] = v.z;
            xs[kv * 4 + 3][r] = v.w;
        }
        __syncthreads();
        if (SELF && ch == 0) {
            constexpr int SDV = SD / 4;
            for (int i = tid; i < 64 * SDV; i += 256) {
                int r = i / SDV, j = i - r * SDV;
                int row = row0 + r;
                if (row < n) {
                    float d = g_dis[OFF_AA + row];
                    float dd = d * d;
                    uint2 raw = *(const uint2*)(selff + (size_t)row * SD + j * 4);
                    float2 f0 = __half22float2(*(__half2*)&raw.x);
                    float2 f1 = __half22float2(*(__half2*)&raw.y);
                    xs[j * 4 + 0][r] += dd * f0.x;
                    xs[j * 4 + 1][r] += dd * f0.y;
                    xs[j * 4 + 2][r] += dd * f1.x;
                    xs[j * 4 + 3][r] += dd * f1.y;
                }
            }
            __syncthreads();
        }
#pragma unroll 4
        for (int k = 0; k < KT; k++) {
            float w[4];
            *(float4*)&w[0] = *(float4*)&Ws[k][c0];
            float xv[4];
#pragma unroll
            for (int i = 0; i < 4; i++) xv[i] = xs[k][r0 + i];
#pragma unroll
            for (int i = 0; i < 4; i++)
#pragma unroll
                for (int j = 0; j < 4; j++) acc[i][j] = fmaf(xv[i], w[j], acc[i][j]);
        }
        __syncthreads();
    }

#pragma unroll
    for (int i = 0; i < 4; i++)
#pragma unroll
        for (int j = 0; j < 4; j++) acc[i][j] += bias[c0 + j];

    if (PROJ) {
        float wp0[4], wp1[4];
#pragma unroll
        for (int j = 0; j < 4; j++) {
            wp0[j] = Wp[(c0 + j) * 2 + 0];
            wp1[j] = Wp[(c0 + j) * 2 + 1];
        }
#pragma unroll
        for (int i = 0; i < 4; i++) {
            float p0 = acc[i][0] * wp0[0] + acc[i][1] * wp0[1]
                     + acc[i][2] * wp0[2] + acc[i][3] * wp0[3];
            float p1 = acc[i][0] * wp1[0] + acc[i][1] * wp1[1]
                     + acc[i][2] * wp1[2] + acc[i][3] * wp1[3];
#pragma unroll
            for (int off = 8; off; off >>= 1) {
                p0 += __shfl_xor_sync(0xFFFFFFFFu, p0, off);
                p1 += __shfl_xor_sync(0xFFFFFFFFu, p1, off);
            }
            int row = row0 + r0 + i;
            if (tx == 0 && row < n) {
                out[(size_t)(row_off + row) * 2 + 0] = p0 + bp[0];
                out[(size_t)(row_off + row) * 2 + 1] = p1 + bp[1];
            }
        }
    } else {
#pragma unroll
        for (int i = 0; i < 4; i++) {
            int row = row0 + r0 + i;
            if (row >= n) continue;
            float v0 = fmaxf(acc[i][0], 0.f), v1 = fmaxf(acc[i][1], 0.f);
            float v2 = fmaxf(acc[i][2], 0.f), v3 = fmaxf(acc[i][3], 0.f);
            __half2 h0 = __floats2half2_rn(v0, v1);
            __half2 h1 = __floats2half2_rn(v2, v3);
            uint2 u; u.x = *(unsigned*)&h0; u.y = *(unsigned*)&h1;
            *(uint2*)(fout + (size_t)(row_off + row) * 64 + c0) = u;
        }
    }
}

// ---------------------------------------------------------------------------
static inline int cdiv(long long a, int b) { return (int)((a + b - 1) / b); }

extern "C" void kernel_launch(void* const* d_in, const int* in_sizes, int n_in,
                              void* d_out, int out_size) {
    const float* x_agent  = (const float*)d_in[1];
    const float* x_target = (const float*)d_in[2];
    const int* src_aa = (const int*)d_in[3];
    const int* dst_aa = (const int*)d_in[4];
    const int* src_at = (const int*)d_in[5];
    const int* dst_at = (const int*)d_in[6];
    const int* src_ta = (const int*)d_in[7];
    const int* dst_ta = (const int*)d_in[8];
    const float* W1_aa = (const float*)d_in[9];
    const float* b1_aa = (const float*)d_in[10];
    const float* W1_at = (const float*)d_in[11];
    const float* b1_at = (const float*)d_in[12];
    const float* W1_ta = (const float*)d_in[13];
    const float* b1_ta = (const float*)d_in[14];
    const float* W2_aa = (const float*)d_in[15];
    const float* b2_aa = (const float*)d_in[16];
    const float* W2_at = (const float*)d_in[17];
    const float* b2_at = (const float*)d_in[18];
    const float* W2_ta = (const float*)d_in[19];
    const float* b2_ta = (const float*)d_in[20];
    const float* Wp_agent  = (const float*)d_in[21];
    const float* bp_agent  = (const float*)d_in[22];
    const float* Wp_target = (const float*)d_in[23];
    const float* bp_target = (const float*)d_in[24];
    float* out = (float*)d_out;

    void *p_x16, *p_f16, *p_a1a, *p_a1t, *p_a2a, *p_a2t;
    cudaGetSymbolAddress(&p_x16, g_x16);
    cudaGetSymbolAddress(&p_f16, g_f16);
    cudaGetSymbolAddress(&p_a1a, g_agg1a);
    cudaGetSymbolAddress(&p_a1t, g_agg1t);
    cudaGetSymbolAddress(&p_a2a, g_agg2a);
    cudaGetSymbolAddress(&p_a2t, g_agg2t);
    const __half* x16 = (const __half*)p_x16;
    const __half* f16 = (const __half*)p_f16;
    float* agg1a = (float*)p_a1a;
    float* agg1t = (float*)p_a1t;
    float* agg2a = (float*)p_a2a;
    float* agg2t = (float*)p_a2t;

    // ---- degrees / norms / CSR / fp16 cast ----
    zero_cnt_kernel<<<cdiv(NTOT, 256), 256>>>();
    constexpr long long CNT_G = (E_AA + 2LL * E_AT + 2LL * E_TA) / 4;
    count_all_kernel<<<cdiv(CNT_G, 256), 256>>>(dst_aa, src_at, dst_at, src_ta, dst_ta);
    cast_kernel<<<cdiv((long long)(NA + NT) * (DIN / 4), 256), 256>>>(
        (const float4*)x_agent, (const float4*)x_target);
    dis_kernel<<<cdiv(NTOT, 256), 256>>>();
    scan_local_kernel<<<NBLK, 1024>>>();
    scan_mid_kernel<<<1, 128>>>();
    scan_add_kernel<<<NBLK, 1024>>>();
    constexpr long long E_TOT = E_AA + E_TA + E_AT;
    fill_kernel<<<cdiv(E_TOT, 256), 256>>>(src_aa, dst_aa, src_ta, dst_ta, src_at, dst_at);

    constexpr long long AGG_THREADS = (long long)(NA + NT) * 32;

    // ---- layer 1: aggregate raw x, then node GEMMs (relu -> f16) ----
    agg_kernel<32><<<cdiv(AGG_THREADS, 256), 256>>>(x16, agg1a, agg1t);
    gemm_kernel<64, true, false><<<cdiv(NA, 64), 256>>>(
        agg1a, x16, NA, 0, W1_aa, W1_ta, b1_aa, b1_ta,
        nullptr, nullptr, (__half*)p_f16, nullptr);
    gemm_kernel<32, false, false><<<cdiv(NT, 64), 256>>>(
        agg1t, nullptr, NT, NA, W1_at, nullptr, b1_at, nullptr,
        nullptr, nullptr, (__half*)p_f16, nullptr);

    // ---- layer 2: aggregate relu features, node GEMMs fused with projection ----
    agg_kernel<64><<<cdiv(AGG_THREADS, 256), 256>>>(f16, agg2a, agg2t);
    gemm_kernel<128, true, true><<<cdiv(NA, 64), 256>>>(
        agg2a, f16, NA, 0, W2_aa, W2_ta, b2_aa, b2_ta,
        Wp_agent, bp_agent, nullptr, out);
    gemm_kernel<64, false, true><<<cdiv(NT, 64), 256>>>(
        agg2t, nullptr, NT, NA, W2_at, nullptr, b2_at, nullptr,
        Wp_target, bp_target, nullptr, out);
}

// round 10
// speedup vs baseline: 1.0912x; 1.0912x over previous
#include <cuda_runtime.h>
#include <cuda_fp16.h>
#include <math.h>

constexpr int NA = 50000;
constexpr int NT = 25000;
constexpr int DIN = 32;
constexpr int H = 64;
constexpr int E_AA = 800000;
constexpr int E_AT = 400000;
constexpr int E_TA = 400000;

constexpr int OFF_AA   = 0;
constexpr int OFF_AT_S = NA;
constexpr int OFF_TA_D = 2 * NA;
constexpr int OFF_AT_D = 3 * NA;
constexpr int OFF_TA_S = 3 * NA + NT;
constexpr int NTOT = 3 * NA + 2 * NT;

constexpr int NBLK_A = (NA + 1023) / 1024;
constexpr int NBLK_T = (NT + 1023) / 1024;
constexpr int NBLK   = NBLK_A + NBLK_T;

// scratch
__device__ int    g_cnt[NTOT];
__device__ __half g_h16_A[(size_t)(NA + NT) * H];   // rows [0,NA)=h_aa, [NA,NA+NT)=h_ta
__device__ __half g_h16_at[(size_t)NA * H];         // agent->target features
__device__ float4 g_acc_a[(size_t)NA * H / 4];
__device__ float4 g_acc_t[(size_t)NT * H / 4];
// CSR (built once per launch; valid for both layers)
__device__ int  g_rs_a[NA + 1];
__device__ int  g_rs_t[NT + 1];
__device__ int  g_cur_a[NA];
__device__ int  g_cur_t[NT];
__device__ int2 g_ent_a[E_AA + E_TA];               // {unified src idx, w bits}
__device__ int2 g_ent_t[E_AT];                      // {agent src idx, w bits}
__device__ int  g_part[NBLK];
__device__ int  g_partscan[NBLK];

// ---------------------------------------------------------------------------
__global__ void zero_cnt_kernel() {
    int i = blockIdx.x * blockDim.x + threadIdx.x;
    if (i < NTOT) g_cnt[i] = 0;
}

__global__ void count_all_kernel(const int* __restrict__ dst_aa,
                                 const int* __restrict__ src_at,
                                 const int* __restrict__ dst_at,
                                 const int* __restrict__ src_ta,
                                 const int* __restrict__ dst_ta) {
    constexpr int G_AA = E_AA / 4, G_AT = E_AT / 4, G_TA = E_TA / 4;
    int i = blockIdx.x * blockDim.x + threadIdx.x;
    const int* p; int off, j;
    if (i < G_AA)                           { p = dst_aa; off = OFF_AA;   j = i; }
    else if (i < G_AA + G_AT)               { p = src_at; off = OFF_AT_S; j = i - G_AA; }
    else if (i < G_AA + 2 * G_AT)           { p = dst_at; off = OFF_AT_D; j = i - G_AA - G_AT; }
    else if (i < G_AA + 2 * G_AT + G_TA)    { p = src_ta; off = OFF_TA_S; j = i - G_AA - 2 * G_AT; }
    else if (i < G_AA + 2 * G_AT + 2*G_TA)  { p = dst_ta; off = OFF_TA_D; j = i - G_AA - 2 * G_AT - G_TA; }
    else return;
    int4 v = *(const int4*)(p + j * 4);
    atomicAdd(&g_cnt[off + v.x], 1);
    atomicAdd(&g_cnt[off + v.y], 1);
    atomicAdd(&g_cnt[off + v.z], 1);
    atomicAdd(&g_cnt[off + v.w], 1);
}

// scan phase 1 (also zeroes fill cursors)
__global__ __launch_bounds__(1024) void scan_local_kernel() {
    __shared__ int sm[1024];
    int b = blockIdx.x;
    bool isA = (b < NBLK_A);
    int base = isA ? b * 1024 : (b - NBLK_A) * 1024;
    int n = isA ? NA : NT;
    int tid = threadIdx.x;
    int i = base + tid;
    int v = 0;
    if (i < n) {
        if (isA) { v = g_cnt[OFF_AA + i] + g_cnt[OFF_TA_D + i]; g_cur_a[i] = 0; }
        else     { v = g_cnt[OFF_AT_D + i];                     g_cur_t[i] = 0; }
    }
    sm[tid] = v;
    __syncthreads();
#pragma unroll
    for (int off = 1; off < 1024; off <<= 1) {
        int u = (tid >= off) ? sm[tid - off] : 0;
        __syncthreads();
        sm[tid] += u;
        __syncthreads();
    }
    if (i < n) {
        int excl = sm[tid] - v;
        if (isA) g_rs_a[i] = excl; else g_rs_t[i] = excl;
    }
    if (tid == 1023) g_part[b] = sm[1023];
}

// scan phase 2
__global__ void scan_mid_kernel() {
    __shared__ int sp[NBLK];
    __shared__ int so[NBLK + 2];
    int tid = threadIdx.x;
    if (tid < NBLK) sp[tid] = g_part[tid];
    __syncthreads();
    if (tid == 0) {
        int s = 0;
        for (int b = 0; b < NBLK_A; b++) { so[b] = s; s += sp[b]; }
        so[NBLK] = s;
        s = 0;
        for (int b = NBLK_A; b < NBLK; b++) { so[b] = s; s += sp[b]; }
        so[NBLK + 1] = s;
    }
    __syncthreads();
    if (tid < NBLK) g_partscan[tid] = so[tid];
    if (tid == 0) { g_rs_a[NA] = so[NBLK]; g_rs_t[NT] = so[NBLK + 1]; }
}

// scan phase 3
__global__ __launch_bounds__(1024) void scan_add_kernel() {
    int b = blockIdx.x;
    if (b == 0) return;
    bool isA = (b < NBLK_A);
    if (!isA && b == NBLK_A) return;
    int base = isA ? b * 1024 : (b - NBLK_A) * 1024;
    int n = isA ? NA : NT;
    int i = base + threadIdx.x;
    int off = g_partscan[b];
    if (i < n) { if (isA) g_rs_a[i] += off; else g_rs_t[i] += off; }
}

// Edge norms computed from degree counts on the fly.
__global__ void fill_kernel(const int* __restrict__ src_aa, const int* __restrict__ dst_aa,
                            const int* __restrict__ src_ta, const int* __restrict__ dst_ta,
                            const int* __restrict__ src_at, const int* __restrict__ dst_at) {
    int i = blockIdx.x * blockDim.x + threadIdx.x;
    if (i < E_AA) {
        int s = src_aa[i], d = dst_aa[i];
        float w = rsqrtf((float)g_cnt[OFF_AA + s] + 1.0f)
                * rsqrtf((float)g_cnt[OFF_AA + d] + 1.0f);
        int pos = g_rs_a[d] + atomicAdd(&g_cur_a[d], 1);
        g_ent_a[pos] = make_int2(s, __float_as_int(w));
    } else if (i < E_AA + E_TA) {
        int j = i - E_AA;
        int s = src_ta[j], d = dst_ta[j];
        float w = rsqrtf((float)g_cnt[OFF_TA_S + s])
                * rsqrtf((float)g_cnt[OFF_TA_D + d]);
        int pos = g_rs_a[d] + atomicAdd(&g_cur_a[d], 1);
        g_ent_a[pos] = make_int2(NA + s, __float_as_int(w));
    } else if (i < E_AA + E_TA + E_AT) {
        int j = i - E_AA - E_TA;
        int s = src_at[j], d = dst_at[j];
        float w = rsqrtf((float)g_cnt[OFF_AT_S + s])
                * rsqrtf((float)g_cnt[OFF_AT_D + d]);
        int pos = g_rs_t[d] + atomicAdd(&g_cur_t[d], 1);
        g_ent_t[pos] = make_int2(s, __float_as_int(w));
    }
}

// Agent transform: writes ONLY fp16 feature buffers (no g_cnt dependence -> race-free
// on the side stream). 512 threads, BM=64, 128 cols, TM=4, TN=4.
template <int K, bool RELU>
__global__ __launch_bounds__(512, 2) void transform_agent_kernel(
        const float4* __restrict__ x,
        const float* __restrict__ Wa, const float* __restrict__ Wb) {
    __shared__ float xs[64][K];
    __shared__ float Ws[K][128];
    int tid = threadIdx.x;
    int row0 = blockIdx.x * 64;
    for (int i = tid; i < K * 64; i += 512) {
        int k = i >> 6, c = i & 63;
        Ws[k][c]      = Wa[i];
        Ws[k][c + 64] = Wb[i];
    }
    constexpr int KV = K / 4;
    for (int i = tid; i < 64 * KV; i += 512) {
        int r = i / KV, kv = i - r * KV;
        int row = row0 + r;
        float4 v = (row < NA) ? x[(size_t)row * KV + kv] : make_float4(0.f, 0.f, 0.f, 0.f);
        if (RELU) { v.x = fmaxf(v.x, 0.f); v.y = fmaxf(v.y, 0.f);
                    v.z = fmaxf(v.z, 0.f); v.w = fmaxf(v.w, 0.f); }
        *(float4*)&xs[r][kv * 4] = v;
    }
    __syncthreads();
    int ty = tid >> 5, tx = tid & 31;
    int r0 = ty * 4, c0 = tx * 4;
    float acc[4][4];
#pragma unroll
    for (int i = 0; i < 4; i++)
#pragma unroll
        for (int j = 0; j < 4; j++) acc[i][j] = 0.f;
#pragma unroll 4
    for (int k = 0; k < K; k++) {
        float w[4];
        *(float4*)&w[0] = *(float4*)&Ws[k][c0];
#pragma unroll
        for (int i = 0; i < 4; i++) {
            float xv = xs[r0 + i][k];
#pragma unroll
            for (int j = 0; j < 4; j++) acc[i][j] = fmaf(xv, w[j], acc[i][j]);
        }
    }
    bool is_a = (c0 < 64);
    int cc = is_a ? c0 : (c0 - 64);
#pragma unroll
    for (int i = 0; i < 4; i++) {
        int row = row0 + r0 + i;
        if (row >= NA) continue;
        __half2 h0 = __floats2half2_rn(acc[i][0], acc[i][1]);
        __half2 h1 = __floats2half2_rn(acc[i][2], acc[i][3]);
        uint2 hpk; hpk.x = *(unsigned*)&h0; hpk.y = *(unsigned*)&h1;
        if (is_a) *(uint2*)(g_h16_A  + (size_t)row * H + cc) = hpk;
        else      *(uint2*)(g_h16_at + (size_t)row * H + cc) = hpk;
    }
}

// Target transform -> g_h16_A rows [NA, NA+NT). 256 threads, BM=64, TM=4, TN=4.
template <int K, bool RELU>
__global__ __launch_bounds__(256, 3) void transform_target_kernel(
        const float4* __restrict__ x, const float* __restrict__ W) {
    __shared__ float xs[64][K];
    __shared__ float Ws[K][64];
    int tid = threadIdx.x;
    int row0 = blockIdx.x * 64;
    for (int i = tid; i < K * 64; i += 256) {
        int k = i >> 6, c = i & 63;
        Ws[k][c] = W[i];
    }
    constexpr int KV = K / 4;
    for (int i = tid; i < 64 * KV; i += 256) {
        int r = i / KV, kv = i - r * KV;
        int row = row0 + r;
        float4 v = (row < NT) ? x[(size_t)row * KV + kv] : make_float4(0.f, 0.f, 0.f, 0.f);
        if (RELU) { v.x = fmaxf(v.x, 0.f); v.y = fmaxf(v.y, 0.f);
                    v.z = fmaxf(v.z, 0.f); v.w = fmaxf(v.w, 0.f); }
        *(float4*)&xs[r][kv * 4] = v;
    }
    __syncthreads();
    int ty = tid >> 4, tx = tid & 15;
    int r0 = ty * 4, c0 = tx * 4;
    float acc[4][4];
#pragma unroll
    for (int i = 0; i < 4; i++)
#pragma unroll
        for (int j = 0; j < 4; j++) acc[i][j] = 0.f;
#pragma unroll 4
    for (int k = 0; k < K; k++) {
        float w[4];
        *(float4*)&w[0] = *(float4*)&Ws[k][c0];
#pragma unroll
        for (int i = 0; i < 4; i++) {
            float xv = xs[r0 + i][k];
#pragma unroll
            for (int j = 0; j < 4; j++) acc[i][j] = fmaf(xv, w[j], acc[i][j]);
        }
    }
#pragma unroll
    for (int i = 0; i < 4; i++) {
        int row = row0 + r0 + i;
        if (row >= NT) continue;
        __half2 h0 = __floats2half2_rn(acc[i][0], acc[i][1]);
        __half2 h1 = __floats2half2_rn(acc[i][2], acc[i][3]);
        uint2 u; u.x = *(unsigned*)&h0; u.y = *(unsigned*)&h1;
        *(uint2*)(g_h16_A + (size_t)(NA + row) * H + c0) = u;
    }
}

// Gather aggregation: warp per dst node, 8 gathers in flight (2-edge unroll x 4 groups).
// Agent epilogue: acc = b_aa + b_ta + d^2 * h_self + edge sum (self term here so the
// layer-1 transforms never touch g_cnt).
__global__ __launch_bounds__(256) void agg_kernel(const float* __restrict__ b_aa,
                                                  const float* __restrict__ b_ta,
                                                  const float* __restrict__ b_at) {
    int gw = (blockIdx.x * 256 + threadIdx.x) >> 5;
    int lane = threadIdx.x & 31;
    int grp = lane >> 3, sub = lane & 7;
    float a[8];
#pragma unroll
    for (int j = 0; j < 8; j++) a[j] = 0.f;
    if (gw < NA) {
        int beg = g_rs_a[gw], end = g_rs_a[gw + 1];
        for (int p = beg + grp; p < end; p += 8) {
            int p2 = p + 4;
            int2 e1 = __ldg(&g_ent_a[p]);
            int2 e2 = (p2 < end) ? __ldg(&g_ent_a[p2]) : make_int2(0, 0);
            float w1 = __int_as_float(e1.y);
            float w2 = __int_as_float(e2.y);
            uint4 r1 = *(const uint4*)(g_h16_A + (size_t)e1.x * H + sub * 8);
            uint4 r2 = *(const uint4*)(g_h16_A + (size_t)e2.x * H + sub * 8);
            float2 f;
            f = __half22float2(*(__half2*)&r1.x); a[0] = fmaf(f.x, w1, a[0]); a[1] = fmaf(f.y, w1, a[1]);
            f = __half22float2(*(__half2*)&r1.y); a[2] = fmaf(f.x, w1, a[2]); a[3] = fmaf(f.y, w1, a[3]);
            f = __half22float2(*(__half2*)&r1.z); a[4] = fmaf(f.x, w1, a[4]); a[5] = fmaf(f.y, w1, a[5]);
            f = __half22float2(*(__half2*)&r1.w); a[6] = fmaf(f.x, w1, a[6]); a[7] = fmaf(f.y, w1, a[7]);
            f = __half22float2(*(__half2*)&r2.x); a[0] = fmaf(f.x, w2, a[0]); a[1] = fmaf(f.y, w2, a[1]);
            f = __half22float2(*(__half2*)&r2.y); a[2] = fmaf(f.x, w2, a[2]); a[3] = fmaf(f.y, w2, a[3]);
            f = __half22float2(*(__half2*)&r2.z); a[4] = fmaf(f.x, w2, a[4]); a[5] = fmaf(f.y, w2, a[5]);
            f = __half22float2(*(__half2*)&r2.w); a[6] = fmaf(f.x, w2, a[6]); a[7] = fmaf(f.y, w2, a[7]);
        }
#pragma unroll
        for (int j = 0; j < 8; j++) {
            a[j] += __shfl_down_sync(0xFFFFFFFFu, a[j], 16);
            a[j] += __shfl_down_sync(0xFFFFFFFFu, a[j], 8);
        }
        if (grp == 0) {
            float dd = 1.0f / ((float)g_cnt[OFF_AA + gw] + 1.0f);   // dis^2
            uint4 rs = *(const uint4*)(g_h16_A + (size_t)gw * H + sub * 8);
            float2 s0 = __half22float2(*(__half2*)&rs.x);
            float2 s1 = __half22float2(*(__half2*)&rs.y);
            float2 s2 = __half22float2(*(__half2*)&rs.z);
            float2 s3 = __half22float2(*(__half2*)&rs.w);
            int c = sub * 8;
            float4 b0, b1;
            b0.x = a[0] + dd * s0.x + b_aa[c + 0] + b_ta[c + 0];
            b0.y = a[1] + dd * s0.y + b_aa[c + 1] + b_ta[c + 1];
            b0.z = a[2] + dd * s1.x + b_aa[c + 2] + b_ta[c + 2];
            b0.w = a[3] + dd * s1.y + b_aa[c + 3] + b_ta[c + 3];
            b1.x = a[4] + dd * s2.x + b_aa[c + 4] + b_ta[c + 4];
            b1.y = a[5] + dd * s2.y + b_aa[c + 5] + b_ta[c + 5];
            b1.z = a[6] + dd * s3.x + b_aa[c + 6] + b_ta[c + 6];
            b1.w = a[7] + dd * s3.y + b_aa[c + 7] + b_ta[c + 7];
            size_t base = (size_t)gw * (H / 4) + sub * 2;
            g_acc_a[base] = b0; g_acc_a[base + 1] = b1;
        }
    } else if (gw < NA + NT) {
        int node = gw - NA;
        int beg = g_rs_t[node], end = g_rs_t[node + 1];
        for (int p = beg + grp; p < end; p += 8) {
            int p2 = p + 4;
            int2 e1 = __ldg(&g_ent_t[p]);
            int2 e2 = (p2 < end) ? __ldg(&g_ent_t[p2]) : make_int2(0, 0);
            float w1 = __int_as_float(e1.y);
            float w2 = __int_as_float(e2.y);
            uint4 r1 = *(const uint4*)(g_h16_at + (size_t)e1.x * H + sub * 8);
            uint4 r2 = *(const uint4*)(g_h16_at + (size_t)e2.x * H + sub * 8);
            float2 f;
            f = __half22float2(*(__half2*)&r1.x); a[0] = fmaf(f.x, w1, a[0]); a[1] = fmaf(f.y, w1, a[1]);
            f = __half22float2(*(__half2*)&r1.y); a[2] = fmaf(f.x, w1, a[2]); a[3] = fmaf(f.y, w1, a[3]);
            f = __half22float2(*(__half2*)&r1.z); a[4] = fmaf(f.x, w1, a[4]); a[5] = fmaf(f.y, w1, a[5]);
            f = __half22float2(*(__half2*)&r1.w); a[6] = fmaf(f.x, w1, a[6]); a[7] = fmaf(f.y, w1, a[7]);
            f = __half22float2(*(__half2*)&r2.x); a[0] = fmaf(f.x, w2, a[0]); a[1] = fmaf(f.y, w2, a[1]);
            f = __half22float2(*(__half2*)&r2.y); a[2] = fmaf(f.x, w2, a[2]); a[3] = fmaf(f.y, w2, a[3]);
            f = __half22float2(*(__half2*)&r2.z); a[4] = fmaf(f.x, w2, a[4]); a[5] = fmaf(f.y, w2, a[5]);
            f = __half22float2(*(__half2*)&r2.w); a[6] = fmaf(f.x, w2, a[6]); a[7] = fmaf(f.y, w2, a[7]);
        }
#pragma unroll
        for (int j = 0; j < 8; j++) {
            a[j] += __shfl_down_sync(0xFFFFFFFFu, a[j], 16);
            a[j] += __shfl_down_sync(0xFFFFFFFFu, a[j], 8);
        }
        if (grp == 0) {
            int c = sub * 8;
            float4 b0 = make_float4(a[0] + b_at[c],     a[1] + b_at[c + 1],
                                    a[2] + b_at[c + 2], a[3] + b_at[c + 3]);
            float4 b1 = make_float4(a[4] + b_at[c + 4], a[5] + b_at[c + 5],
                                    a[6] + b_at[c + 6], a[7] + b_at[c + 7]);
            size_t base = (size_t)node * (H / 4) + sub * 2;
            g_acc_t[base] = b0; g_acc_t[base + 1] = b1;
        }
    }
}

// One warp per row; both node types in one launch.
__global__ void proj_kernel(const float* __restrict__ Wp_a, const float* __restrict__ bp_a,
                            const float* __restrict__ Wp_t, const float* __restrict__ bp_t,
                            float* __restrict__ out) {
    int idx = blockIdx.x * blockDim.x + threadIdx.x;
    int row = idx >> 5, lane = idx & 31;
    if (row >= NA + NT) return;
    const float* g; const float* Wp; const float* bp; float* o;
    if (row < NA) {
        g = (const float*)g_acc_a + (size_t)row * H;
        Wp = Wp_a; bp = bp_a; o = out + (size_t)row * 2;
    } else {
        g = (const float*)g_acc_t + (size_t)(row - NA) * H;
        Wp = Wp_t; bp = bp_t; o = out + (size_t)row * 2;
    }
    float g0 = g[lane];
    float g1 = g[lane + 32];
    float p0 = g0 * Wp[lane * 2 + 0] + g1 * Wp[(lane + 32) * 2 + 0];
    float p1 = g0 * Wp[lane * 2 + 1] + g1 * Wp[(lane + 32) * 2 + 1];
#pragma unroll
    for (int off = 16; off; off >>= 1) {
        p0 += __shfl_down_sync(0xFFFFFFFFu, p0, off);
        p1 += __shfl_down_sync(0xFFFFFFFFu, p1, off);
    }
    if (lane == 0) { o[0] = p0 + bp[0]; o[1] = p1 + bp[1]; }
}

// ---------------------------------------------------------------------------
static inline int cdiv(long long a, int b) { return (int)((a + b - 1) / b); }

extern "C" void kernel_launch(void* const* d_in, const int* in_sizes, int n_in,
                              void* d_out, int out_size) {
    const float* x_agent  = (const float*)d_in[1];
    const float* x_target = (const float*)d_in[2];
    const int* src_aa = (const int*)d_in[3];
    const int* dst_aa = (const int*)d_in[4];
    const int* src_at = (const int*)d_in[5];
    const int* dst_at = (const int*)d_in[6];
    const int* src_ta = (const int*)d_in[7];
    const int* dst_ta = (const int*)d_in[8];
    const float* W1_aa = (const float*)d_in[9];
    const float* b1_aa = (const float*)d_in[10];
    const float* W1_at = (const float*)d_in[11];
    const float* b1_at = (const float*)d_in[12];
    const float* W1_ta = (const float*)d_in[13];
    const float* b1_ta = (const float*)d_in[14];
    const float* W2_aa = (const float*)d_in[15];
    const float* b2_aa = (const float*)d_in[16];
    const float* W2_at = (const float*)d_in[17];
    const float* b2_at = (const float*)d_in[18];
    const float* W2_ta = (const float*)d_in[19];
    const float* b2_ta = (const float*)d_in[20];
    const float* Wp_agent  = (const float*)d_in[21];
    const float* bp_agent  = (const float*)d_in[22];
    const float* Wp_target = (const float*)d_in[23];
    const float* bp_target = (const float*)d_in[24];
    float* out = (float*)d_out;

    void *p_acca, *p_acct;
    cudaGetSymbolAddress(&p_acca, g_acc_a);
    cudaGetSymbolAddress(&p_acct, g_acc_t);
    float* acc_a = (float*)p_acca;
    float* acc_t = (float*)p_acct;

    // Side stream + events, created once (host-side handles only; no device mem).
    static cudaStream_t s2 = nullptr;
    static cudaEvent_t evFork = nullptr, evJoin = nullptr;
    if (s2 == nullptr) {
        cudaStreamCreateWithFlags(&s2, cudaStreamNonBlocking);
        cudaEventCreateWithFlags(&evFork, cudaEventDisableTiming);
        cudaEventCreateWithFlags(&evJoin, cudaEventDisableTiming);
    }

    // ---- fork: layer-1 transforms (read ONLY inputs/weights) on s2 ----
    cudaEventRecord(evFork, 0);
    cudaStreamWaitEvent(s2, evFork, 0);
    transform_agent_kernel<DIN, false><<<cdiv(NA, 64), 512, 0, s2>>>(
        (const float4*)x_agent, W1_aa, W1_at);
    transform_target_kernel<DIN, false><<<cdiv(NT, 64), 256, 0, s2>>>(
        (const float4*)x_target, W1_ta);
    cudaEventRecord(evJoin, s2);

    // ---- main stream: degrees / scan / CSR fill ----
    zero_cnt_kernel<<<cdiv(NTOT, 256), 256>>>();
    constexpr long long CNT_G = (E_AA + 2LL * E_AT + 2LL * E_TA) / 4;
    count_all_kernel<<<cdiv(CNT_G, 256), 256>>>(dst_aa, src_at, dst_at, src_ta, dst_ta);
    scan_local_kernel<<<NBLK, 1024>>>();
    scan_mid_kernel<<<1, 128>>>();
    scan_add_kernel<<<NBLK, 1024>>>();
    constexpr long long E_TOT = E_AA + E_TA + E_AT;
    fill_kernel<<<cdiv(E_TOT, 256), 256>>>(src_aa, dst_aa, src_ta, dst_ta, src_at, dst_at);

    // ---- join, then layer-1 aggregate ----
    cudaStreamWaitEvent(0, evJoin, 0);
    constexpr long long AGG_THREADS = (long long)(NA + NT) * 32;
    agg_kernel<<<cdiv(AGG_THREADS, 256), 256>>>(b1_aa, b1_ta, b1_at);

    // ---- layer 2 ----
    transform_agent_kernel<H, true><<<cdiv(NA, 64), 512>>>(
        (const float4*)acc_a, W2_aa, W2_at);
    transform_target_kernel<H, true><<<cdiv(NT, 64), 256>>>(
        (const float4*)acc_t, W2_ta);
    agg_kernel<<<cdiv(AGG_THREADS, 256), 256>>>(b2_aa, b2_ta, b2_at);

    // ---- output projection ----
    proj_kernel<<<cdiv((long long)(NA + NT) * 32, 256), 256>>>(
        Wp_agent, bp_agent, Wp_target, bp_target, out);
}

// round 11
// speedup vs baseline: 1.1507x; 1.0545x over previous
#include <cuda_runtime.h>
#include <cuda_fp16.h>
#include <math.h>

constexpr int NA = 50000;
constexpr int NT = 25000;
constexpr int DIN = 32;
constexpr int H = 64;
constexpr int E_AA = 800000;
constexpr int E_AT = 400000;
constexpr int E_TA = 400000;

constexpr int OFF_AA   = 0;
constexpr int OFF_AT_S = NA;
constexpr int OFF_TA_D = 2 * NA;
constexpr int OFF_AT_D = 3 * NA;
constexpr int OFF_TA_S = 3 * NA + NT;
constexpr int NTOT = 3 * NA + 2 * NT;

constexpr int NBLK_A = (NA + 1023) / 1024;
constexpr int NBLK_T = (NT + 1023) / 1024;
constexpr int NBLK   = NBLK_A + NBLK_T;

// scratch
__device__ int    g_cnt[NTOT];
__device__ __half g_h16_A[(size_t)(NA + NT) * H];   // rows [0,NA)=h_aa, [NA,NA+NT)=h_ta
__device__ __half g_h16_at[(size_t)NA * H];         // agent->target features
__device__ float4 g_acc_a[(size_t)NA * H / 4];
__device__ float4 g_acc_t[(size_t)NT * H / 4];
// CSR (built once per launch; valid for both layers)
__device__ int  g_rs_a[NA + 1];
__device__ int  g_rs_t[NT + 1];
__device__ int  g_cur_a[NA];
__device__ int  g_cur_t[NT];
__device__ int2 g_ent_a[E_AA + E_TA];               // {unified src idx, w bits}
__device__ int2 g_ent_t[E_AT];                      // {agent src idx, w bits}
__device__ int  g_part[NBLK];
__device__ int  g_partscan[NBLK];

// ---------------------------------------------------------------------------
__global__ void zero_cnt_kernel() {
    int i = blockIdx.x * blockDim.x + threadIdx.x;
    if (i < NTOT) g_cnt[i] = 0;
}

__global__ void count_all_kernel(const int* __restrict__ dst_aa,
                                 const int* __restrict__ src_at,
                                 const int* __restrict__ dst_at,
                                 const int* __restrict__ src_ta,
                                 const int* __restrict__ dst_ta) {
    constexpr int G_AA = E_AA / 4, G_AT = E_AT / 4, G_TA = E_TA / 4;
    int i = blockIdx.x * blockDim.x + threadIdx.x;
    const int* p; int off, j;
    if (i < G_AA)                           { p = dst_aa; off = OFF_AA;   j = i; }
    else if (i < G_AA + G_AT)               { p = src_at; off = OFF_AT_S; j = i - G_AA; }
    else if (i < G_AA + 2 * G_AT)           { p = dst_at; off = OFF_AT_D; j = i - G_AA - G_AT; }
    else if (i < G_AA + 2 * G_AT + G_TA)    { p = src_ta; off = OFF_TA_S; j = i - G_AA - 2 * G_AT; }
    else if (i < G_AA + 2 * G_AT + 2*G_TA)  { p = dst_ta; off = OFF_TA_D; j = i - G_AA - 2 * G_AT - G_TA; }
    else return;
    int4 v = *(const int4*)(p + j * 4);
    atomicAdd(&g_cnt[off + v.x], 1);
    atomicAdd(&g_cnt[off + v.y], 1);
    atomicAdd(&g_cnt[off + v.z], 1);
    atomicAdd(&g_cnt[off + v.w], 1);
}

// scan phase 1 (also zeroes fill cursors)
__global__ __launch_bounds__(1024) void scan_local_kernel() {
    __shared__ int sm[1024];
    int b = blockIdx.x;
    bool isA = (b < NBLK_A);
    int base = isA ? b * 1024 : (b - NBLK_A) * 1024;
    int n = isA ? NA : NT;
    int tid = threadIdx.x;
    int i = base + tid;
    int v = 0;
    if (i < n) {
        if (isA) { v = g_cnt[OFF_AA + i] + g_cnt[OFF_TA_D + i]; g_cur_a[i] = 0; }
        else     { v = g_cnt[OFF_AT_D + i];                     g_cur_t[i] = 0; }
    }
    sm[tid] = v;
    __syncthreads();
#pragma unroll
    for (int off = 1; off < 1024; off <<= 1) {
        int u = (tid >= off) ? sm[tid - off] : 0;
        __syncthreads();
        sm[tid] += u;
        __syncthreads();
    }
    if (i < n) {
        int excl = sm[tid] - v;
        if (isA) g_rs_a[i] = excl; else g_rs_t[i] = excl;
    }
    if (tid == 1023) g_part[b] = sm[1023];
}

// scan phase 2
__global__ void scan_mid_kernel() {
    __shared__ int sp[NBLK];
    __shared__ int so[NBLK + 2];
    int tid = threadIdx.x;
    if (tid < NBLK) sp[tid] = g_part[tid];
    __syncthreads();
    if (tid == 0) {
        int s = 0;
        for (int b = 0; b < NBLK_A; b++) { so[b] = s; s += sp[b]; }
        so[NBLK] = s;
        s = 0;
        for (int b = NBLK_A; b < NBLK; b++) { so[b] = s; s += sp[b]; }
        so[NBLK + 1] = s;
    }
    __syncthreads();
    if (tid < NBLK) g_partscan[tid] = so[tid];
    if (tid == 0) { g_rs_a[NA] = so[NBLK]; g_rs_t[NT] = so[NBLK + 1]; }
}

// scan phase 3
__global__ __launch_bounds__(1024) void scan_add_kernel() {
    int b = blockIdx.x;
    if (b == 0) return;
    bool isA = (b < NBLK_A);
    if (!isA && b == NBLK_A) return;
    int base = isA ? b * 1024 : (b - NBLK_A) * 1024;
    int n = isA ? NA : NT;
    int i = base + threadIdx.x;
    int off = g_partscan[b];
    if (i < n) { if (isA) g_rs_a[i] += off; else g_rs_t[i] += off; }
}

// Edge norms computed from degree counts on the fly.
__global__ void fill_kernel(const int* __restrict__ src_aa, const int* __restrict__ dst_aa,
                            const int* __restrict__ src_ta, const int* __restrict__ dst_ta,
                            const int* __restrict__ src_at, const int* __restrict__ dst_at) {
    int i = blockIdx.x * blockDim.x + threadIdx.x;
    if (i < E_AA) {
        int s = src_aa[i], d = dst_aa[i];
        float w = rsqrtf((float)g_cnt[OFF_AA + s] + 1.0f)
                * rsqrtf((float)g_cnt[OFF_AA + d] + 1.0f);
        int pos = g_rs_a[d] + atomicAdd(&g_cur_a[d], 1);
        g_ent_a[pos] = make_int2(s, __float_as_int(w));
    } else if (i < E_AA + E_TA) {
        int j = i - E_AA;
        int s = src_ta[j], d = dst_ta[j];
        float w = rsqrtf((float)g_cnt[OFF_TA_S + s])
                * rsqrtf((float)g_cnt[OFF_TA_D + d]);
        int pos = g_rs_a[d] + atomicAdd(&g_cur_a[d], 1);
        g_ent_a[pos] = make_int2(NA + s, __float_as_int(w));
    } else if (i < E_AA + E_TA + E_AT) {
        int j = i - E_AA - E_TA;
        int s = src_at[j], d = dst_at[j];
        float w = rsqrtf((float)g_cnt[OFF_AT_S + s])
                * rsqrtf((float)g_cnt[OFF_AT_D + d]);
        int pos = g_rs_t[d] + atomicAdd(&g_cur_t[d], 1);
        g_ent_t[pos] = make_int2(s, __float_as_int(w));
    }
}

// Agent transform: writes ONLY fp16 feature buffers. 512 threads, BM=64, 128 cols,
// TM=4, TN=4. smem 48KB -> 3+ blocks/SM allowed.
template <int K, bool RELU>
__global__ __launch_bounds__(512, 3) void transform_agent_kernel(
        const float4* __restrict__ x,
        const float* __restrict__ Wa, const float* __restrict__ Wb) {
    __shared__ float xs[64][K];
    __shared__ float Ws[K][128];
    int tid = threadIdx.x;
    int row0 = blockIdx.x * 64;
    for (int i = tid; i < K * 64; i += 512) {
        int k = i >> 6, c = i & 63;
        Ws[k][c]      = Wa[i];
        Ws[k][c + 64] = Wb[i];
    }
    constexpr int KV = K / 4;
    for (int i = tid; i < 64 * KV; i += 512) {
        int r = i / KV, kv = i - r * KV;
        int row = row0 + r;
        float4 v = (row < NA) ? x[(size_t)row * KV + kv] : make_float4(0.f, 0.f, 0.f, 0.f);
        if (RELU) { v.x = fmaxf(v.x, 0.f); v.y = fmaxf(v.y, 0.f);
                    v.z = fmaxf(v.z, 0.f); v.w = fmaxf(v.w, 0.f); }
        *(float4*)&xs[r][kv * 4] = v;
    }
    __syncthreads();
    int ty = tid >> 5, tx = tid & 31;
    int r0 = ty * 4, c0 = tx * 4;
    float acc[4][4];
#pragma unroll
    for (int i = 0; i < 4; i++)
#pragma unroll
        for (int j = 0; j < 4; j++) acc[i][j] = 0.f;
#pragma unroll 4
    for (int k = 0; k < K; k++) {
        float w[4];
        *(float4*)&w[0] = *(float4*)&Ws[k][c0];
#pragma unroll
        for (int i = 0; i < 4; i++) {
            float xv = xs[r0 + i][k];
#pragma unroll
            for (int j = 0; j < 4; j++) acc[i][j] = fmaf(xv, w[j], acc[i][j]);
        }
    }
    bool is_a = (c0 < 64);
    int cc = is_a ? c0 : (c0 - 64);
#pragma unroll
    for (int i = 0; i < 4; i++) {
        int row = row0 + r0 + i;
        if (row >= NA) continue;
        __half2 h0 = __floats2half2_rn(acc[i][0], acc[i][1]);
        __half2 h1 = __floats2half2_rn(acc[i][2], acc[i][3]);
        uint2 hpk; hpk.x = *(unsigned*)&h0; hpk.y = *(unsigned*)&h1;
        if (is_a) *(uint2*)(g_h16_A  + (size_t)row * H + cc) = hpk;
        else      *(uint2*)(g_h16_at + (size_t)row * H + cc) = hpk;
    }
}

// Target transform -> g_h16_A rows [NA, NA+NT). 256 threads, BM=64, TM=4, TN=4.
template <int K, bool RELU>
__global__ __launch_bounds__(256, 4) void transform_target_kernel(
        const float4* __restrict__ x, const float* __restrict__ W) {
    __shared__ float xs[64][K];
    __shared__ float Ws[K][64];
    int tid = threadIdx.x;
    int row0 = blockIdx.x * 64;
    for (int i = tid; i < K * 64; i += 256) {
        int k = i >> 6, c = i & 63;
        Ws[k][c] = W[i];
    }
    constexpr int KV = K / 4;
    for (int i = tid; i < 64 * KV; i += 256) {
        int r = i / KV, kv = i - r * KV;
        int row = row0 + r;
        float4 v = (row < NT) ? x[(size_t)row * KV + kv] : make_float4(0.f, 0.f, 0.f, 0.f);
        if (RELU) { v.x = fmaxf(v.x, 0.f); v.y = fmaxf(v.y, 0.f);
                    v.z = fmaxf(v.z, 0.f); v.w = fmaxf(v.w, 0.f); }
        *(float4*)&xs[r][kv * 4] = v;
    }
    __syncthreads();
    int ty = tid >> 4, tx = tid & 15;
    int r0 = ty * 4, c0 = tx * 4;
    float acc[4][4];
#pragma unroll
    for (int i = 0; i < 4; i++)
#pragma unroll
        for (int j = 0; j < 4; j++) acc[i][j] = 0.f;
#pragma unroll 4
    for (int k = 0; k < K; k++) {
        float w[4];
        *(float4*)&w[0] = *(float4*)&Ws[k][c0];
#pragma unroll
        for (int i = 0; i < 4; i++) {
            float xv = xs[r0 + i][k];
#pragma unroll
            for (int j = 0; j < 4; j++) acc[i][j] = fmaf(xv, w[j], acc[i][j]);
        }
    }
#pragma unroll
    for (int i = 0; i < 4; i++) {
        int row = row0 + r0 + i;
        if (row >= NT) continue;
        __half2 h0 = __floats2half2_rn(acc[i][0], acc[i][1]);
        __half2 h1 = __floats2half2_rn(acc[i][2], acc[i][3]);
        uint2 u; u.x = *(unsigned*)&h0; u.y = *(unsigned*)&h1;
        *(uint2*)(g_h16_A + (size_t)(NA + row) * H + c0) = u;
    }
}

// Gather aggregation: warp per dst node, 8 gathers in flight (2-edge unroll x 4 groups).
// Agent epilogue adds b_aa + b_ta + d^2 * h_self.
__global__ __launch_bounds__(256) void agg_kernel(const float* __restrict__ b_aa,
                                                  const float* __restrict__ b_ta,
                                                  const float* __restrict__ b_at) {
    int gw = (blockIdx.x * 256 + threadIdx.x) >> 5;
    int lane = threadIdx.x & 31;
    int grp = lane >> 3, sub = lane & 7;
    float a[8];
#pragma unroll
    for (int j = 0; j < 8; j++) a[j] = 0.f;
    if (gw < NA) {
        int beg = g_rs_a[gw], end = g_rs_a[gw + 1];
        for (int p = beg + grp; p < end; p += 8) {
            int p2 = p + 4;
            int2 e1 = __ldg(&g_ent_a[p]);
            int2 e2 = (p2 < end) ? __ldg(&g_ent_a[p2]) : make_int2(0, 0);
            float w1 = __int_as_float(e1.y);
            float w2 = __int_as_float(e2.y);
            uint4 r1 = *(const uint4*)(g_h16_A + (size_t)e1.x * H + sub * 8);
            uint4 r2 = *(const uint4*)(g_h16_A + (size_t)e2.x * H + sub * 8);
            float2 f;
            f = __half22float2(*(__half2*)&r1.x); a[0] = fmaf(f.x, w1, a[0]); a[1] = fmaf(f.y, w1, a[1]);
            f = __half22float2(*(__half2*)&r1.y); a[2] = fmaf(f.x, w1, a[2]); a[3] = fmaf(f.y, w1, a[3]);
            f = __half22float2(*(__half2*)&r1.z); a[4] = fmaf(f.x, w1, a[4]); a[5] = fmaf(f.y, w1, a[5]);
            f = __half22float2(*(__half2*)&r1.w); a[6] = fmaf(f.x, w1, a[6]); a[7] = fmaf(f.y, w1, a[7]);
            f = __half22float2(*(__half2*)&r2.x); a[0] = fmaf(f.x, w2, a[0]); a[1] = fmaf(f.y, w2, a[1]);
            f = __half22float2(*(__half2*)&r2.y); a[2] = fmaf(f.x, w2, a[2]); a[3] = fmaf(f.y, w2, a[3]);
            f = __half22float2(*(__half2*)&r2.z); a[4] = fmaf(f.x, w2, a[4]); a[5] = fmaf(f.y, w2, a[5]);
            f = __half22float2(*(__half2*)&r2.w); a[6] = fmaf(f.x, w2, a[6]); a[7] = fmaf(f.y, w2, a[7]);
        }
#pragma unroll
        for (int j = 0; j < 8; j++) {
            a[j] += __shfl_down_sync(0xFFFFFFFFu, a[j], 16);
            a[j] += __shfl_down_sync(0xFFFFFFFFu, a[j], 8);
        }
        if (grp == 0) {
            float dd = 1.0f / ((float)g_cnt[OFF_AA + gw] + 1.0f);   // dis^2
            uint4 rs = *(const uint4*)(g_h16_A + (size_t)gw * H + sub * 8);
            float2 s0 = __half22float2(*(__half2*)&rs.x);
            float2 s1 = __half22float2(*(__half2*)&rs.y);
            float2 s2 = __half22float2(*(__half2*)&rs.z);
            float2 s3 = __half22float2(*(__half2*)&rs.w);
            int c = sub * 8;
            float4 b0, b1;
            b0.x = a[0] + dd * s0.x + b_aa[c + 0] + b_ta[c + 0];
            b0.y = a[1] + dd * s0.y + b_aa[c + 1] + b_ta[c + 1];
            b0.z = a[2] + dd * s1.x + b_aa[c + 2] + b_ta[c + 2];
            b0.w = a[3] + dd * s1.y + b_aa[c + 3] + b_ta[c + 3];
            b1.x = a[4] + dd * s2.x + b_aa[c + 4] + b_ta[c + 4];
            b1.y = a[5] + dd * s2.y + b_aa[c + 5] + b_ta[c + 5];
            b1.z = a[6] + dd * s3.x + b_aa[c + 6] + b_ta[c + 6];
            b1.w = a[7] + dd * s3.y + b_aa[c + 7] + b_ta[c + 7];
            size_t base = (size_t)gw * (H / 4) + sub * 2;
            g_acc_a[base] = b0; g_acc_a[base + 1] = b1;
        }
    } else if (gw < NA + NT) {
        int node = gw - NA;
        int beg = g_rs_t[node], end = g_rs_t[node + 1];
        for (int p = beg + grp; p < end; p += 8) {
            int p2 = p + 4;
            int2 e1 = __ldg(&g_ent_t[p]);
            int2 e2 = (p2 < end) ? __ldg(&g_ent_t[p2]) : make_int2(0, 0);
            float w1 = __int_as_float(e1.y);
            float w2 = __int_as_float(e2.y);
            uint4 r1 = *(const uint4*)(g_h16_at + (size_t)e1.x * H + sub * 8);
            uint4 r2 = *(const uint4*)(g_h16_at + (size_t)e2.x * H + sub * 8);
            float2 f;
            f = __half22float2(*(__half2*)&r1.x); a[0] = fmaf(f.x, w1, a[0]); a[1] = fmaf(f.y, w1, a[1]);
            f = __half22float2(*(__half2*)&r1.y); a[2] = fmaf(f.x, w1, a[2]); a[3] = fmaf(f.y, w1, a[3]);
            f = __half22float2(*(__half2*)&r1.z); a[4] = fmaf(f.x, w1, a[4]); a[5] = fmaf(f.y, w1, a[5]);
            f = __half22float2(*(__half2*)&r1.w); a[6] = fmaf(f.x, w1, a[6]); a[7] = fmaf(f.y, w1, a[7]);
            f = __half22float2(*(__half2*)&r2.x); a[0] = fmaf(f.x, w2, a[0]); a[1] = fmaf(f.y, w2, a[1]);
            f = __half22float2(*(__half2*)&r2.y); a[2] = fmaf(f.x, w2, a[2]); a[3] = fmaf(f.y, w2, a[3]);
            f = __half22float2(*(__half2*)&r2.z); a[4] = fmaf(f.x, w2, a[4]); a[5] = fmaf(f.y, w2, a[5]);
            f = __half22float2(*(__half2*)&r2.w); a[6] = fmaf(f.x, w2, a[6]); a[7] = fmaf(f.y, w2, a[7]);
        }
#pragma unroll
        for (int j = 0; j < 8; j++) {
            a[j] += __shfl_down_sync(0xFFFFFFFFu, a[j], 16);
            a[j] += __shfl_down_sync(0xFFFFFFFFu, a[j], 8);
        }
        if (grp == 0) {
            int c = sub * 8;
            float4 b0 = make_float4(a[0] + b_at[c],     a[1] + b_at[c + 1],
                                    a[2] + b_at[c + 2], a[3] + b_at[c + 3]);
            float4 b1 = make_float4(a[4] + b_at[c + 4], a[5] + b_at[c + 5],
                                    a[6] + b_at[c + 6], a[7] + b_at[c + 7]);
            size_t base = (size_t)node * (H / 4) + sub * 2;
            g_acc_t[base] = b0; g_acc_t[base + 1] = b1;
        }
    }
}

// One warp per row; both node types in one launch.
__global__ void proj_kernel(const float* __restrict__ Wp_a, const float* __restrict__ bp_a,
                            const float* __restrict__ Wp_t, const float* __restrict__ bp_t,
                            float* __restrict__ out) {
    int idx = blockIdx.x * blockDim.x + threadIdx.x;
    int row = idx >> 5, lane = idx & 31;
    if (row >= NA + NT) return;
    const float* g; const float* Wp; const float* bp; float* o;
    if (row < NA) {
        g = (const float*)g_acc_a + (size_t)row * H;
        Wp = Wp_a; bp = bp_a; o = out + (size_t)row * 2;
    } else {
        g = (const float*)g_acc_t + (size_t)(row - NA) * H;
        Wp = Wp_t; bp = bp_t; o = out + (size_t)row * 2;
    }
    float g0 = g[lane];
    float g1 = g[lane + 32];
    float p0 = g0 * Wp[lane * 2 + 0] + g1 * Wp[(lane + 32) * 2 + 0];
    float p1 = g0 * Wp[lane * 2 + 1] + g1 * Wp[(lane + 32) * 2 + 1];
#pragma unroll
    for (int off = 16; off; off >>= 1) {
        p0 += __shfl_down_sync(0xFFFFFFFFu, p0, off);
        p1 += __shfl_down_sync(0xFFFFFFFFu, p1, off);
    }
    if (lane == 0) { o[0] = p0 + bp[0]; o[1] = p1 + bp[1]; }
}

// ---------------------------------------------------------------------------
static inline int cdiv(long long a, int b) { return (int)((a + b - 1) / b); }

extern "C" void kernel_launch(void* const* d_in, const int* in_sizes, int n_in,
                              void* d_out, int out_size) {
    const float* x_agent  = (const float*)d_in[1];
    const float* x_target = (const float*)d_in[2];
    const int* src_aa = (const int*)d_in[3];
    const int* dst_aa = (const int*)d_in[4];
    const int* src_at = (const int*)d_in[5];
    const int* dst_at = (const int*)d_in[6];
    const int* src_ta = (const int*)d_in[7];
    const int* dst_ta = (const int*)d_in[8];
    const float* W1_aa = (const float*)d_in[9];
    const float* b1_aa = (const float*)d_in[10];
    const float* W1_at = (const float*)d_in[11];
    const float* b1_at = (const float*)d_in[12];
    const float* W1_ta = (const float*)d_in[13];
    const float* b1_ta = (const float*)d_in[14];
    const float* W2_aa = (const float*)d_in[15];
    const float* b2_aa = (const float*)d_in[16];
    const float* W2_at = (const float*)d_in[17];
    const float* b2_at = (const float*)d_in[18];
    const float* W2_ta = (const float*)d_in[19];
    const float* b2_ta = (const float*)d_in[20];
    const float* Wp_agent  = (const float*)d_in[21];
    const float* bp_agent  = (const float*)d_in[22];
    const float* Wp_target = (const float*)d_in[23];
    const float* bp_target = (const float*)d_in[24];
    float* out = (float*)d_out;

    void *p_acca, *p_acct;
    cudaGetSymbolAddress(&p_acca, g_acc_a);
    cudaGetSymbolAddress(&p_acct, g_acc_t);
    float* acc_a = (float*)p_acca;
    float* acc_t = (float*)p_acct;

    // Side stream + events, created once (host-side handles only; no device mem).
    static cudaStream_t s2 = nullptr;
    static cudaEvent_t evFork = nullptr, evJoin = nullptr, evFork2 = nullptr, evJoin2 = nullptr;
    if (s2 == nullptr) {
        cudaStreamCreateWithFlags(&s2, cudaStreamNonBlocking);
        cudaEventCreateWithFlags(&evFork, cudaEventDisableTiming);
        cudaEventCreateWithFlags(&evJoin, cudaEventDisableTiming);
        cudaEventCreateWithFlags(&evFork2, cudaEventDisableTiming);
        cudaEventCreateWithFlags(&evJoin2, cudaEventDisableTiming);
    }

    // ---- fork 1: layer-1 transforms (read ONLY inputs/weights) on s2 ----
    cudaEventRecord(evFork, 0);
    cudaStreamWaitEvent(s2, evFork, 0);
    transform_agent_kernel<DIN, false><<<cdiv(NA, 64), 512, 0, s2>>>(
        (const float4*)x_agent, W1_aa, W1_at);
    transform_target_kernel<DIN, false><<<cdiv(NT, 64), 256, 0, s2>>>(
        (const float4*)x_target, W1_ta);
    cudaEventRecord(evJoin, s2);

    // ---- main stream: degrees / scan / CSR fill ----
    zero_cnt_kernel<<<cdiv(NTOT, 256), 256>>>();
    constexpr long long CNT_G = (E_AA + 2LL * E_AT + 2LL * E_TA) / 4;
    count_all_kernel<<<cdiv(CNT_G, 256), 256>>>(dst_aa, src_at, dst_at, src_ta, dst_ta);
    scan_local_kernel<<<NBLK, 1024>>>();
    scan_mid_kernel<<<1, 128>>>();
    scan_add_kernel<<<NBLK, 1024>>>();
    constexpr long long E_TOT = E_AA + E_TA + E_AT;
    fill_kernel<<<cdiv(E_TOT, 256), 256>>>(src_aa, dst_aa, src_ta, dst_ta, src_at, dst_at);

    // ---- join 1, layer-1 aggregate ----
    cudaStreamWaitEvent(0, evJoin, 0);
    constexpr long long AGG_THREADS = (long long)(NA + NT) * 32;
    agg_kernel<<<cdiv(AGG_THREADS, 256), 256>>>(b1_aa, b1_ta, b1_at);

    // ---- fork 2: layer-2 transforms in parallel (agent on main, target on s2) ----
    cudaEventRecord(evFork2, 0);
    cudaStreamWaitEvent(s2, evFork2, 0);
    transform_target_kernel<H, true><<<cdiv(NT, 64), 256, 0, s2>>>(
        (const float4*)acc_t, W2_ta);
    cudaEventRecord(evJoin2, s2);
    transform_agent_kernel<H, true><<<cdiv(NA, 64), 512>>>(
        (const float4*)acc_a, W2_aa, W2_at);
    cudaStreamWaitEvent(0, evJoin2, 0);

    // ---- layer-2 aggregate + projection ----
    agg_kernel<<<cdiv(AGG_THREADS, 256), 256>>>(b2_aa, b2_ta, b2_at);
    proj_kernel<<<cdiv((long long)(NA + NT) * 32, 256), 256>>>(
        Wp_agent, bp_agent, Wp_target, bp_target, out);
}